// round 2
// baseline (speedup 1.0000x reference)
#include <cuda_runtime.h>
#include <cuda_bf16.h>
#include <math.h>

// Problem constants
#define GRAVITY_C 9.81f
#define W_INERTIA 1.0f
#define W_GRAVITY 0.01f
#define W_STRAIN  1.0f

// Global accumulator (double for stable summation under atomics)
__device__ double g_acc;

__global__ void zero_kernel() {
    if (threadIdx.x == 0 && blockIdx.x == 0) g_acc = 0.0;
}

// -------- block reduction helper (double) --------
__device__ __forceinline__ double block_reduce(double v) {
    #pragma unroll
    for (int off = 16; off > 0; off >>= 1)
        v += __shfl_down_sync(0xFFFFFFFFu, v, off);
    __shared__ double sh[32];
    int lane = threadIdx.x & 31;
    int wid  = threadIdx.x >> 5;
    if (lane == 0) sh[wid] = v;
    __syncthreads();
    int nwarps = (blockDim.x + 31) >> 5;
    v = (threadIdx.x < nwarps) ? sh[threadIdx.x] : 0.0;
    if (wid == 0) {
        #pragma unroll
        for (int off = 16; off > 0; off >>= 1)
            v += __shfl_down_sync(0xFFFFFFFFu, v, off);
    }
    return v; // valid in thread 0
}

// -------- vertex kernel: inertia + gravity --------
__global__ void vertex_kernel(const float* __restrict__ pos_next,
                              const float* __restrict__ pos_curr,
                              const float* __restrict__ pos_prev,
                              const float* __restrict__ mass,
                              int V) {
    double local = 0.0;
    const double inv3V = 1.0 / (3.0 * (double)V);
    const double invV  = 1.0 / (double)V;
    for (int v = blockIdx.x * blockDim.x + threadIdx.x; v < V;
         v += gridDim.x * blockDim.x) {
        float m = mass[v];
        float nx = pos_next[3*v+0], ny = pos_next[3*v+1], nz = pos_next[3*v+2];
        float cx = pos_curr[3*v+0], cy = pos_curr[3*v+1], cz = pos_curr[3*v+2];
        float px = pos_prev[3*v+0], py = pos_prev[3*v+1], pz = pos_prev[3*v+2];
        float ax = nx + px - 2.0f * cx;
        float ay = ny + py - 2.0f * cy;
        float az = nz + pz - 2.0f * cz;
        float a2 = ax*ax + ay*ay + az*az;
        local += (double)(0.5f * m * a2) * (W_INERTIA * inv3V)
               - (double)(m * GRAVITY_C * cy) * (W_GRAVITY * invV);
    }
    double bsum = block_reduce(local);
    if (threadIdx.x == 0) atomicAdd(&g_acc, bsum);
}

// -------- element kernel: Neo-Hookean strain --------
__global__ void element_kernel(const float* __restrict__ pos_next,
                               const int* __restrict__ elements,
                               const float* __restrict__ rest_volumes,
                               const float* __restrict__ rest_inv,
                               const float* __restrict__ lam_p,
                               const float* __restrict__ mu_p,
                               int E) {
    const float lam = lam_p[0];
    const float mu  = mu_p[0];
    const double invE = 1.0 / (double)E;
    double local = 0.0;

    for (int e = blockIdx.x * blockDim.x + threadIdx.x; e < E;
         e += gridDim.x * blockDim.x) {
        // element indices: 4 x int32, 16B aligned -> single vector load
        const int4 idx = reinterpret_cast<const int4*>(elements)[e];
        const int i0 = idx.x, i1 = idx.y, i2 = idx.z, i3 = idx.w;

        float v0x = pos_next[3*i0+0], v0y = pos_next[3*i0+1], v0z = pos_next[3*i0+2];
        float v1x = pos_next[3*i1+0], v1y = pos_next[3*i1+1], v1z = pos_next[3*i1+2];
        float v2x = pos_next[3*i2+0], v2y = pos_next[3*i2+1], v2z = pos_next[3*i2+2];
        float v3x = pos_next[3*i3+0], v3y = pos_next[3*i3+1], v3z = pos_next[3*i3+2];

        // Ds columns: c0 = v1-v0, c1 = v2-v0, c2 = v3-v0
        float d00 = v1x - v0x, d01 = v2x - v0x, d02 = v3x - v0x;
        float d10 = v1y - v0y, d11 = v2y - v0y, d12 = v3y - v0y;
        float d20 = v1z - v0z, d21 = v2z - v0z, d22 = v3z - v0z;

        // rest_inv row-major 3x3 at e*9
        const float* R = rest_inv + (size_t)e * 9;
        float r00 = R[0], r01 = R[1], r02 = R[2];
        float r10 = R[3], r11 = R[4], r12 = R[5];
        float r20 = R[6], r21 = R[7], r22 = R[8];

        // F = Ds * R
        float f00 = d00*r00 + d01*r10 + d02*r20;
        float f01 = d00*r01 + d01*r11 + d02*r21;
        float f02 = d00*r02 + d01*r12 + d02*r22;
        float f10 = d10*r00 + d11*r10 + d12*r20;
        float f11 = d10*r01 + d11*r11 + d12*r21;
        float f12 = d10*r02 + d11*r12 + d12*r22;
        float f20 = d20*r00 + d21*r10 + d22*r20;
        float f21 = d20*r01 + d21*r11 + d22*r21;
        float f22 = d20*r02 + d21*r12 + d22*r22;

        float det = f00 * (f11*f22 - f12*f21)
                  - f01 * (f10*f22 - f12*f20)
                  + f02 * (f10*f21 - f11*f20);
        det = fmaxf(det, 1e-8f);
        float logd = logf(det);

        float tr = f00*f00 + f01*f01 + f02*f02
                 + f10*f10 + f11*f11 + f12*f12
                 + f20*f20 + f21*f21 + f22*f22;

        float psi = 0.5f * lam * logd * logd - mu * logd + 0.5f * mu * (tr - 3.0f);
        local += (double)(psi * rest_volumes[e]) * (W_STRAIN * invE);
    }
    double bsum = block_reduce(local);
    if (threadIdx.x == 0) atomicAdd(&g_acc, bsum);
}

__global__ void finalize_kernel(float* __restrict__ out) {
    if (threadIdx.x == 0 && blockIdx.x == 0) out[0] = (float)g_acc;
}

extern "C" void kernel_launch(void* const* d_in, const int* in_sizes, int n_in,
                              void* d_out, int out_size) {
    const float* pos_next = (const float*)d_in[0];
    const float* pos_curr = (const float*)d_in[1];
    const float* pos_prev = (const float*)d_in[2];
    const float* mass     = (const float*)d_in[3];
    const int*   elements = (const int*)d_in[4];
    const float* rest_vol = (const float*)d_in[5];
    const float* rest_inv = (const float*)d_in[6];
    const float* lam      = (const float*)d_in[7];
    const float* mu       = (const float*)d_in[8];
    float* out = (float*)d_out;

    const int V = in_sizes[0] / 3;   // pos_next has V*3 elements
    const int E = in_sizes[5];       // rest_volumes has E elements

    zero_kernel<<<1, 32>>>();

    {
        int threads = 256;
        int blocks  = (V + threads - 1) / threads;
        if (blocks > 2048) blocks = 2048;
        vertex_kernel<<<blocks, threads>>>(pos_next, pos_curr, pos_prev, mass, V);
    }
    {
        int threads = 256;
        int blocks  = (E + threads - 1) / threads;
        if (blocks > 8192) blocks = 8192;
        element_kernel<<<blocks, threads>>>(pos_next, elements, rest_vol,
                                            rest_inv, lam, mu, E);
    }
    finalize_kernel<<<1, 32>>>(out);
}

// round 3
// speedup vs baseline: 1.0290x; 1.0290x over previous
#include <cuda_runtime.h>
#include <cuda_bf16.h>
#include <math.h>

#define GRAVITY_C 9.81f
#define W_INERTIA 1.0f
#define W_GRAVITY 0.01f
#define W_STRAIN  1.0f

#define MAX_V 500000
#define EBLK 256

// Global accumulator + padded position buffer (device globals: allowed scratch)
__device__ double g_acc;
__device__ float4 g_pos4[MAX_V];

__global__ void zero_kernel() {
    if (threadIdx.x == 0 && blockIdx.x == 0) g_acc = 0.0;
}

// -------- block reduction helper (double) --------
__device__ __forceinline__ double block_reduce(double v) {
    #pragma unroll
    for (int off = 16; off > 0; off >>= 1)
        v += __shfl_down_sync(0xFFFFFFFFu, v, off);
    __shared__ double sh[32];
    int lane = threadIdx.x & 31;
    int wid  = threadIdx.x >> 5;
    if (lane == 0) sh[wid] = v;
    __syncthreads();
    int nwarps = (blockDim.x + 31) >> 5;
    v = (threadIdx.x < nwarps) ? sh[threadIdx.x] : 0.0;
    if (wid == 0) {
        #pragma unroll
        for (int off = 16; off > 0; off >>= 1)
            v += __shfl_down_sync(0xFFFFFFFFu, v, off);
    }
    return v;
}

// -------- vertex kernel: inertia + gravity + pack pos_next into float4 --------
__global__ void vertex_kernel(const float* __restrict__ pos_next,
                              const float* __restrict__ pos_curr,
                              const float* __restrict__ pos_prev,
                              const float* __restrict__ mass,
                              int V) {
    double local = 0.0;
    const double inv3V = 1.0 / (3.0 * (double)V);
    const double invV  = 1.0 / (double)V;
    for (int v = blockIdx.x * blockDim.x + threadIdx.x; v < V;
         v += gridDim.x * blockDim.x) {
        float m = mass[v];
        float nx = pos_next[3*v+0], ny = pos_next[3*v+1], nz = pos_next[3*v+2];
        float cx = pos_curr[3*v+0], cy = pos_curr[3*v+1], cz = pos_curr[3*v+2];
        float px = pos_prev[3*v+0], py = pos_prev[3*v+1], pz = pos_prev[3*v+2];
        // pack for fast element-kernel gather
        g_pos4[v] = make_float4(nx, ny, nz, 0.0f);
        float ax = nx + px - 2.0f * cx;
        float ay = ny + py - 2.0f * cy;
        float az = nz + pz - 2.0f * cz;
        float a2 = ax*ax + ay*ay + az*az;
        local += (double)(0.5f * m * a2) * (W_INERTIA * inv3V)
               - (double)(m * GRAVITY_C * cy) * (W_GRAVITY * invV);
    }
    double bsum = block_reduce(local);
    if (threadIdx.x == 0) atomicAdd(&g_acc, bsum);
}

// -------- element kernel: Neo-Hookean strain (padded gather + smem-staged rest_inv) --------
__global__ void __launch_bounds__(EBLK)
element_kernel(const int* __restrict__ elements,
               const float* __restrict__ rest_volumes,
               const float* __restrict__ rest_inv,
               const float* __restrict__ lam_p,
               const float* __restrict__ mu_p,
               int E) {
    __shared__ float sR[EBLK * 9];

    const int blockBase = blockIdx.x * EBLK;
    const int nElem = min(EBLK, E - blockBase);
    const int nFloats = nElem * 9;

    // coalesced stage of this block's rest_inv rows into shared
    const float* Rg = rest_inv + (size_t)blockBase * 9;
    for (int i = threadIdx.x; i < nFloats; i += EBLK)
        sR[i] = Rg[i];
    __syncthreads();

    const float lam = lam_p[0];
    const float mu  = mu_p[0];
    const double invE = 1.0 / (double)E;
    double local = 0.0;

    const int e = blockBase + threadIdx.x;
    if (e < E) {
        const int4 idx = reinterpret_cast<const int4*>(elements)[e];

        float4 v0 = g_pos4[idx.x];
        float4 v1 = g_pos4[idx.y];
        float4 v2 = g_pos4[idx.z];
        float4 v3 = g_pos4[idx.w];

        // Ds columns: c0 = v1-v0, c1 = v2-v0, c2 = v3-v0
        float d00 = v1.x - v0.x, d01 = v2.x - v0.x, d02 = v3.x - v0.x;
        float d10 = v1.y - v0.y, d11 = v2.y - v0.y, d12 = v3.y - v0.y;
        float d20 = v1.z - v0.z, d21 = v2.z - v0.z, d22 = v3.z - v0.z;

        const float* R = sR + threadIdx.x * 9;
        float r00 = R[0], r01 = R[1], r02 = R[2];
        float r10 = R[3], r11 = R[4], r12 = R[5];
        float r20 = R[6], r21 = R[7], r22 = R[8];

        // F = Ds * R
        float f00 = d00*r00 + d01*r10 + d02*r20;
        float f01 = d00*r01 + d01*r11 + d02*r21;
        float f02 = d00*r02 + d01*r12 + d02*r22;
        float f10 = d10*r00 + d11*r10 + d12*r20;
        float f11 = d10*r01 + d11*r11 + d12*r21;
        float f12 = d10*r02 + d11*r12 + d12*r22;
        float f20 = d20*r00 + d21*r10 + d22*r20;
        float f21 = d20*r01 + d21*r11 + d22*r21;
        float f22 = d20*r02 + d21*r12 + d22*r22;

        float det = f00 * (f11*f22 - f12*f21)
                  - f01 * (f10*f22 - f12*f20)
                  + f02 * (f10*f21 - f11*f20);
        det = fmaxf(det, 1e-8f);
        float logd = logf(det);

        float tr = f00*f00 + f01*f01 + f02*f02
                 + f10*f10 + f11*f11 + f12*f12
                 + f20*f20 + f21*f21 + f22*f22;

        float psi = 0.5f * lam * logd * logd - mu * logd + 0.5f * mu * (tr - 3.0f);
        local = (double)(psi * rest_volumes[e]) * (W_STRAIN * invE);
    }
    double bsum = block_reduce(local);
    if (threadIdx.x == 0) atomicAdd(&g_acc, bsum);
}

// Fallback element kernel (unpadded gather) in case V exceeds MAX_V
__global__ void element_kernel_fallback(const float* __restrict__ pos_next,
                                        const int* __restrict__ elements,
                                        const float* __restrict__ rest_volumes,
                                        const float* __restrict__ rest_inv,
                                        const float* __restrict__ lam_p,
                                        const float* __restrict__ mu_p,
                                        int E) {
    const float lam = lam_p[0];
    const float mu  = mu_p[0];
    const double invE = 1.0 / (double)E;
    double local = 0.0;
    for (int e = blockIdx.x * blockDim.x + threadIdx.x; e < E;
         e += gridDim.x * blockDim.x) {
        const int4 idx = reinterpret_cast<const int4*>(elements)[e];
        const int i0 = idx.x, i1 = idx.y, i2 = idx.z, i3 = idx.w;
        float v0x = pos_next[3*i0+0], v0y = pos_next[3*i0+1], v0z = pos_next[3*i0+2];
        float v1x = pos_next[3*i1+0], v1y = pos_next[3*i1+1], v1z = pos_next[3*i1+2];
        float v2x = pos_next[3*i2+0], v2y = pos_next[3*i2+1], v2z = pos_next[3*i2+2];
        float v3x = pos_next[3*i3+0], v3y = pos_next[3*i3+1], v3z = pos_next[3*i3+2];
        float d00 = v1x - v0x, d01 = v2x - v0x, d02 = v3x - v0x;
        float d10 = v1y - v0y, d11 = v2y - v0y, d12 = v3y - v0y;
        float d20 = v1z - v0z, d21 = v2z - v0z, d22 = v3z - v0z;
        const float* R = rest_inv + (size_t)e * 9;
        float r00 = R[0], r01 = R[1], r02 = R[2];
        float r10 = R[3], r11 = R[4], r12 = R[5];
        float r20 = R[6], r21 = R[7], r22 = R[8];
        float f00 = d00*r00 + d01*r10 + d02*r20;
        float f01 = d00*r01 + d01*r11 + d02*r21;
        float f02 = d00*r02 + d01*r12 + d02*r22;
        float f10 = d10*r00 + d11*r10 + d12*r20;
        float f11 = d10*r01 + d11*r11 + d12*r21;
        float f12 = d10*r02 + d11*r12 + d12*r22;
        float f20 = d20*r00 + d21*r10 + d22*r20;
        float f21 = d20*r01 + d21*r11 + d22*r21;
        float f22 = d20*r02 + d21*r12 + d22*r22;
        float det = f00 * (f11*f22 - f12*f21)
                  - f01 * (f10*f22 - f12*f20)
                  + f02 * (f10*f21 - f11*f20);
        det = fmaxf(det, 1e-8f);
        float logd = logf(det);
        float tr = f00*f00 + f01*f01 + f02*f02
                 + f10*f10 + f11*f11 + f12*f12
                 + f20*f20 + f21*f21 + f22*f22;
        float psi = 0.5f * lam * logd * logd - mu * logd + 0.5f * mu * (tr - 3.0f);
        local += (double)(psi * rest_volumes[e]) * (W_STRAIN * invE);
    }
    double bsum = block_reduce(local);
    if (threadIdx.x == 0) atomicAdd(&g_acc, bsum);
}

__global__ void finalize_kernel(float* __restrict__ out) {
    if (threadIdx.x == 0 && blockIdx.x == 0) out[0] = (float)g_acc;
}

extern "C" void kernel_launch(void* const* d_in, const int* in_sizes, int n_in,
                              void* d_out, int out_size) {
    const float* pos_next = (const float*)d_in[0];
    const float* pos_curr = (const float*)d_in[1];
    const float* pos_prev = (const float*)d_in[2];
    const float* mass     = (const float*)d_in[3];
    const int*   elements = (const int*)d_in[4];
    const float* rest_vol = (const float*)d_in[5];
    const float* rest_inv = (const float*)d_in[6];
    const float* lam      = (const float*)d_in[7];
    const float* mu       = (const float*)d_in[8];
    float* out = (float*)d_out;

    const int V = in_sizes[0] / 3;
    const int E = in_sizes[5];

    zero_kernel<<<1, 32>>>();

    {
        int threads = 256;
        int blocks  = (V + threads - 1) / threads;
        if (blocks > 4096) blocks = 4096;
        vertex_kernel<<<blocks, threads>>>(pos_next, pos_curr, pos_prev, mass, V);
    }

    if (V <= MAX_V) {
        int blocks = (E + EBLK - 1) / EBLK;
        element_kernel<<<blocks, EBLK>>>(elements, rest_vol, rest_inv, lam, mu, E);
    } else {
        int threads = 256;
        int blocks  = (E + threads - 1) / threads;
        if (blocks > 8192) blocks = 8192;
        element_kernel_fallback<<<blocks, threads>>>(pos_next, elements, rest_vol,
                                                     rest_inv, lam, mu, E);
    }

    finalize_kernel<<<1, 32>>>(out);
}